// round 2
// baseline (speedup 1.0000x reference)
#include <cuda_runtime.h>
#include <cuda_bf16.h>
#include <math.h>

// ---------------- problem constants ----------------
#define NPTS    524288
#define GRID_D  300
#define NCOMP   36
#define SDF_DIM 256
#define OUT_CH  129      // 1 + APP_DIM
#define IN_CH   129      // 21 embed + 108 feat
#define IN_PAD  132      // padded to multiple of 4
#define OUT_PAD 132
#define BP      64       // points per block
#define NBLK    (NPTS / BP)   // 8192

// smem: A[64][132] + H[64][260]
#define H_PITCH 260
#define SMEM_FLOATS (BP * IN_PAD + BP * H_PITCH)
#define SMEM_BYTES  (SMEM_FLOATS * 4)

// ---------------- scratch (device globals; no allocation allowed) ----------------
__device__ __align__(16) float g_planesT[3 * GRID_D * GRID_D * NCOMP]; // [p][y][x][c]
__device__ __align__(16) float g_linesT[3 * GRID_D * NCOMP];           // [p][z][c]
__device__ __align__(16) float g_w1T[IN_PAD * SDF_DIM];                // [k_new][j], rows 129..131 zero
__device__ __align__(16) float g_w2T[SDF_DIM * OUT_PAD];               // [j][o],   cols 129..131 zero

// ---------------- preprocess: plane transpose [3][36][300][300] -> [3][300][300][36] ----------------
__global__ void transpose_planes_kernel(const float* __restrict__ planes) {
    // grid = 3 * 300 * 10 blocks; each block handles one (p, y, 32-wide x tile)
    int b = blockIdx.x;
    int xt = b % 10;
    int rest = b / 10;
    int y = rest % GRID_D;
    int p = rest / GRID_D;
    int x0 = xt * 32;

    __shared__ float tile[NCOMP][33];

    for (int idx = threadIdx.x; idx < NCOMP * 32; idx += blockDim.x) {
        int c = idx >> 5;
        int xx = idx & 31;
        if (x0 + xx < GRID_D)
            tile[c][xx] = planes[((p * NCOMP + c) * GRID_D + y) * GRID_D + x0 + xx];
    }
    __syncthreads();
    for (int idx = threadIdx.x; idx < 32 * NCOMP; idx += blockDim.x) {
        int xx = idx / NCOMP;
        int c  = idx % NCOMP;
        if (x0 + xx < GRID_D)
            g_planesT[((p * GRID_D + y) * GRID_D + (x0 + xx)) * NCOMP + c] = tile[c][xx];
    }
}

// ---------------- preprocess: w1 (permute+transpose+pad), w2 (transpose+pad), lines transpose ----------------
// new input-channel order: [feat(108) = orig 21..128, embed(21) = orig 0..20, pad(3)=0]
__global__ void prep_small_kernel(const float* __restrict__ w1,
                                  const float* __restrict__ w2,
                                  const float* __restrict__ lines) {
    int i = blockIdx.x * blockDim.x + threadIdx.x;
    const int W1T_N = IN_PAD * SDF_DIM;     // 33792
    const int W2T_N = SDF_DIM * OUT_PAD;    // 33792
    const int LNT_N = 3 * GRID_D * NCOMP;   // 32400
    if (i < W1T_N) {
        int k = i >> 8;          // new channel index
        int j = i & 255;
        float v = 0.0f;
        if (k < IN_CH) {
            int orig = (k < 108) ? (21 + k) : (k - 108);
            v = w1[j * IN_CH + orig];
        }
        g_w1T[i] = v;
    } else if (i < W1T_N + W2T_N) {
        int t = i - W1T_N;
        int j = t / OUT_PAD;
        int o = t % OUT_PAD;
        g_w2T[t] = (o < OUT_CH) ? w2[o * SDF_DIM + j] : 0.0f;
    } else if (i < W1T_N + W2T_N + LNT_N) {
        int t = i - W1T_N - W2T_N;
        int c = t % NCOMP;
        int z = (t / NCOMP) % GRID_D;
        int p = t / (NCOMP * GRID_D);
        g_linesT[t] = lines[(p * NCOMP + c) * GRID_D + z];
    }
}

// ---------------- activation: softplus(100u)/100 ----------------
__device__ __forceinline__ float actf(float u) {
    float t = 100.0f * u;
    if (t > 15.0f) return u;              // log1p(exp(t)) ~= t, err < 4e-9
    return log1pf(__expf(t)) * 0.01f;     // underflows cleanly to 0 for very negative t
}

__device__ __forceinline__ void fma_acc(float4& acc, float4 a,
                                        float4 b0, float4 b1, float4 b2, float4 b3) {
    acc.x += a.x * b0.x; acc.x += a.y * b1.x; acc.x += a.z * b2.x; acc.x += a.w * b3.x;
    acc.y += a.x * b0.y; acc.y += a.y * b1.y; acc.y += a.z * b2.y; acc.y += a.w * b3.y;
    acc.z += a.x * b0.z; acc.z += a.y * b1.z; acc.z += a.z * b2.z; acc.z += a.w * b3.z;
    acc.w += a.x * b0.w; acc.w += a.y * b1.w; acc.w += a.z * b2.w; acc.w += a.w * b3.w;
}

// ---------------- fused main kernel ----------------
__global__ __launch_bounds__(256, 2)
void tensosdf_main_kernel(const float* __restrict__ xyz,
                          const float* __restrict__ b1,
                          const float* __restrict__ b2,
                          float* __restrict__ out) {
    extern __shared__ float sm[];
    float* A_s = sm;                     // [64][132]  mlp_in (permuted layout)
    float* H_s = sm + BP * IN_PAD;       // [64][260]  hidden activations

    const int tid = threadIdx.x;
    const int pt0 = blockIdx.x * BP;

    // ---- Phase A: features + embedding into A_s ----
    if (tid < 192) {
        // one (point, plane) task per thread
        int point = tid / 3;
        int p     = tid - point * 3;
        int gp = pt0 + point;
        float x = xyz[gp * 3 + 0];
        float y = xyz[gp * 3 + 1];
        float z = xyz[gp * 3 + 2];
        float sx, sy, sz;
        if (p == 0)      { sx = x; sy = y; sz = z; }
        else if (p == 1) { sx = x; sy = z; sz = y; }
        else             { sx = y; sy = z; sz = x; }

        const float HALF = 0.5f * (GRID_D - 1);
        float fx = (sx + 1.0f) * HALF;
        float fy = (sy + 1.0f) * HALF;
        float fz = (sz + 1.0f) * HALF;
        int x0 = min(max((int)floorf(fx), 0), GRID_D - 2);
        int y0 = min(max((int)floorf(fy), 0), GRID_D - 2);
        int z0 = min(max((int)floorf(fz), 0), GRID_D - 2);
        float tx = fx - (float)x0;
        float ty = fy - (float)y0;
        float tz = fz - (float)z0;

        float w00 = (1.0f - tx) * (1.0f - ty);
        float w01 = tx * (1.0f - ty);
        float w10 = (1.0f - tx) * ty;
        float w11 = tx * ty;

        const float4* base = (const float4*)(g_planesT + (size_t)((p * GRID_D + y0) * GRID_D + x0) * NCOMP);
        const float4* lb   = (const float4*)(g_linesT + (size_t)(p * GRID_D + z0) * NCOMP);
        // strides in float4 units: next x = 9, next y row = 2700
        float* dst = A_s + point * IN_PAD + p * NCOMP;   // feat block at cols [p*36, p*36+36)
        #pragma unroll
        for (int cc = 0; cc < 9; cc++) {
            float4 v00 = base[cc];
            float4 v01 = base[9 + cc];
            float4 v10 = base[2700 + cc];
            float4 v11 = base[2709 + cc];
            float4 l0 = lb[cc];
            float4 l1 = lb[9 + cc];
            float4 r;
            r.x = (v00.x * w00 + v01.x * w01 + v10.x * w10 + v11.x * w11) * (l0.x + (l1.x - l0.x) * tz);
            r.y = (v00.y * w00 + v01.y * w01 + v10.y * w10 + v11.y * w11) * (l0.y + (l1.y - l0.y) * tz);
            r.z = (v00.z * w00 + v01.z * w01 + v10.z * w10 + v11.z * w11) * (l0.z + (l1.z - l0.z) * tz);
            r.w = (v00.w * w00 + v01.w * w01 + v10.w * w10 + v11.w * w11) * (l0.w + (l1.w - l0.w) * tz);
            ((float4*)dst)[cc] = r;
        }
    } else {
        // embedding: one point per thread (64 threads -> 64 points)
        int point = tid - 192;
        int gp = pt0 + point;
        float v[3];
        v[0] = xyz[gp * 3 + 0];
        v[1] = xyz[gp * 3 + 1];
        v[2] = xyz[gp * 3 + 2];
        float* dst = A_s + point * IN_PAD + 108;   // embed block at cols [108,129)
        dst[0] = v[0]; dst[1] = v[1]; dst[2] = v[2];
        #pragma unroll
        for (int d = 0; d < 3; d++) {
            #pragma unroll
            for (int f = 0; f < 3; f++) {
                float s, c;
                sincosf(v[d] * (float)(1 << f), &s, &c);
                dst[3 + d * 3 + f]  = s;
                dst[12 + d * 3 + f] = c;
            }
        }
        dst[21] = 0.0f; dst[22] = 0.0f; dst[23] = 0.0f;   // pad cols 129..131
    }
    __syncthreads();

    const int wid  = tid >> 5;
    const int lane = tid & 31;
    const int ib   = wid * 8;   // this warp's 8 points

    // ---- GEMM1: H = act(A @ w1T + b1), N=256 in 2 passes of 128 ----
    #pragma unroll 1
    for (int pass = 0; pass < 2; pass++) {
        const int j0 = pass * 128 + lane * 4;
        float4 bias = *(const float4*)(b1 + j0);
        float4 acc[8];
        #pragma unroll
        for (int i = 0; i < 8; i++) acc[i] = bias;

        const float* wbase = g_w1T + j0;
        const float* abase = A_s + ib * IN_PAD;
        #pragma unroll 1
        for (int kq = 0; kq < IN_PAD / 4; kq++) {
            const float* wk = wbase + kq * 4 * SDF_DIM;
            float4 b0 = *(const float4*)(wk);
            float4 b1v = *(const float4*)(wk + SDF_DIM);
            float4 b2v = *(const float4*)(wk + 2 * SDF_DIM);
            float4 b3v = *(const float4*)(wk + 3 * SDF_DIM);
            #pragma unroll
            for (int i = 0; i < 8; i++) {
                float4 a = *(const float4*)(abase + i * IN_PAD + kq * 4);
                fma_acc(acc[i], a, b0, b1v, b2v, b3v);
            }
        }
        #pragma unroll
        for (int i = 0; i < 8; i++) {
            float4 h;
            h.x = actf(acc[i].x);
            h.y = actf(acc[i].y);
            h.z = actf(acc[i].z);
            h.w = actf(acc[i].w);
            *(float4*)(H_s + (ib + i) * H_PITCH + j0) = h;
        }
    }
    __syncthreads();

    // ---- GEMM2: out = H @ w2T + b2 (o in [0,128) here; o=128 in cleanup) ----
    {
        const int o0 = lane * 4;
        float4 bias = *(const float4*)(b2 + o0);
        float4 acc[8];
        #pragma unroll
        for (int i = 0; i < 8; i++) acc[i] = bias;

        const float* wbase = g_w2T + o0;
        const float* hbase = H_s + ib * H_PITCH;
        #pragma unroll 1
        for (int jq = 0; jq < SDF_DIM / 4; jq++) {
            const float* wk = wbase + jq * 4 * OUT_PAD;
            float4 c0 = *(const float4*)(wk);
            float4 c1 = *(const float4*)(wk + OUT_PAD);
            float4 c2 = *(const float4*)(wk + 2 * OUT_PAD);
            float4 c3 = *(const float4*)(wk + 3 * OUT_PAD);
            #pragma unroll
            for (int i = 0; i < 8; i++) {
                float4 a = *(const float4*)(hbase + i * H_PITCH + jq * 4);
                fma_acc(acc[i], a, c0, c1, c2, c3);
            }
        }
        #pragma unroll
        for (int i = 0; i < 8; i++) {
            float* op = out + (size_t)(pt0 + ib + i) * OUT_CH + o0;
            op[0] = acc[i].x; op[1] = acc[i].y; op[2] = acc[i].z; op[3] = acc[i].w;
        }
    }

    // ---- cleanup: output channel o = 128 (one thread per point) ----
    if (tid < BP) {
        float acc = b2[128];
        const float* hp = H_s + tid * H_PITCH;
        #pragma unroll 4
        for (int j = 0; j < SDF_DIM; j += 4) {
            float4 h4 = *(const float4*)(hp + j);
            acc += h4.x * g_w2T[(j + 0) * OUT_PAD + 128];
            acc += h4.y * g_w2T[(j + 1) * OUT_PAD + 128];
            acc += h4.z * g_w2T[(j + 2) * OUT_PAD + 128];
            acc += h4.w * g_w2T[(j + 3) * OUT_PAD + 128];
        }
        out[(size_t)(pt0 + tid) * OUT_CH + 128] = acc;
    }
}

// ---------------- launch ----------------
extern "C" void kernel_launch(void* const* d_in, const int* in_sizes, int n_in,
                              void* d_out, int out_size) {
    const float* xyz    = (const float*)d_in[0];
    const float* planes = (const float*)d_in[1];
    const float* lines  = (const float*)d_in[2];
    const float* w1     = (const float*)d_in[3];
    const float* b1     = (const float*)d_in[4];
    const float* w2     = (const float*)d_in[5];
    const float* b2     = (const float*)d_in[6];
    float* out = (float*)d_out;

    cudaFuncSetAttribute(tensosdf_main_kernel,
                         cudaFuncAttributeMaxDynamicSharedMemorySize, SMEM_BYTES);

    transpose_planes_kernel<<<3 * GRID_D * 10, 256>>>(planes);

    const int prep_total = IN_PAD * SDF_DIM + SDF_DIM * OUT_PAD + 3 * GRID_D * NCOMP;
    prep_small_kernel<<<(prep_total + 255) / 256, 256>>>(w1, w2, lines);

    tensosdf_main_kernel<<<NBLK, 256, SMEM_BYTES>>>(xyz, b1, b2, out);
}